// round 7
// baseline (speedup 1.0000x reference)
#include <cuda_runtime.h>
#include <cstdint>
#include <cstddef>

// Problem constants
#define SEQ   577
#define BB    64
#define DD    768
#define HH    12
#define KK    8
#define PP    576            // SEQ-1
#define ROWS  (PP*BB)        // 36864
#define S2    (SEQ*SEQ)      // 332929
#define EPSC  1e-8f
#define BETA_C  3.0f
#define GAMMA_C 5.0f

#define DBLK  1152           // kernel D blocks: 1152*32 = 36864 rows

// ---------------- scratch (static device globals; no allocation) -------------
__device__ __align__(16) float g_fg[ROWS];
__device__ __align__(16) float g_anom[ROWS];
__device__ __align__(16) float g_gate[ROWS];

// ---------------- helpers ----------------------------------------------------
typedef unsigned long long u64;

// sm_103a has no redux.sync.f32 — butterfly shuffle reduction instead.
__device__ __forceinline__ float warp_sum(float v) {
    v += __shfl_xor_sync(0xffffffffu, v, 16);
    v += __shfl_xor_sync(0xffffffffu, v, 8);
    v += __shfl_xor_sync(0xffffffffu, v, 4);
    v += __shfl_xor_sync(0xffffffffu, v, 2);
    v += __shfl_xor_sync(0xffffffffu, v, 1);
    return v;
}
__device__ __forceinline__ float warp_max(float v) {
    v = fmaxf(v, __shfl_xor_sync(0xffffffffu, v, 16));
    v = fmaxf(v, __shfl_xor_sync(0xffffffffu, v, 8));
    v = fmaxf(v, __shfl_xor_sync(0xffffffffu, v, 4));
    v = fmaxf(v, __shfl_xor_sync(0xffffffffu, v, 2));
    v = fmaxf(v, __shfl_xor_sync(0xffffffffu, v, 1));
    return v;
}
__device__ __forceinline__ u64 pk2(float lo, float hi) {
    u64 r; asm("mov.b64 %0, {%1,%2};" : "=l"(r) : "f"(lo), "f"(hi)); return r;
}
__device__ __forceinline__ void up2(u64 v, float& lo, float& hi) {
    asm("mov.b64 {%0,%1}, %2;" : "=f"(lo), "=f"(hi) : "l"(v));
}
__device__ __forceinline__ u64 f2mul(u64 a, u64 b) {
    u64 d; asm("mul.rn.f32x2 %0, %1, %2;" : "=l"(d) : "l"(a), "l"(b)); return d;
}
__device__ __forceinline__ u64 f2fma(u64 a, u64 b, u64 c) {
    u64 d; asm("fma.rn.f32x2 %0, %1, %2, %3;" : "=l"(d) : "l"(a), "l"(b), "l"(c)); return d;
}

// ---------------- Kernel A: foreground mask ----------------------------------
// grid = (BB), block = 576. One thread per patch. cls_attn = mean over H of
// attn[b,h,0,1+p]; per-b mean/std (ddof=1, two-pass); fg = cls_attn > mu+1.5*sigma.
__global__ void __launch_bounds__(576) ka_fg(const float* __restrict__ attn) {
    __shared__ float sp[18];
    __shared__ float bcast;
    const int b = blockIdx.x;
    const int p = threadIdx.x;
    const int lane = p & 31, w = p >> 5;

    const float* base = attn + (size_t)b * HH * (size_t)S2 + 1 + p;
    float a = 0.f;
    #pragma unroll
    for (int h = 0; h < HH; h++) a += __ldg(base + (size_t)h * S2);
    a *= (1.0f / 12.0f);

    // block sum -> mu
    float v = warp_sum(a);
    if (lane == 0) sp[w] = v;
    __syncthreads();
    if (w == 0) {
        float t = (lane < 18) ? sp[lane] : 0.f;
        t = warp_sum(t);
        if (lane == 0) bcast = t;
    }
    __syncthreads();
    const float mu = bcast * (1.0f / 576.0f);
    const float d = a - mu;
    __syncthreads();  // before smem reuse

    // block sum of squared deviations -> sigma (ddof=1)
    v = warp_sum(d * d);
    if (lane == 0) sp[w] = v;
    __syncthreads();
    if (w == 0) {
        float t = (lane < 18) ? sp[lane] : 0.f;
        t = warp_sum(t);
        if (lane == 0) bcast = t;
    }
    __syncthreads();
    const float sigma = sqrtf(bcast * (1.0f / 575.0f));

    g_fg[p * BB + b] = (a > mu + 1.5f * sigma) ? 1.0f : 0.0f;
}

// ---------------- Kernel B: per-row anomaly ----------------------------------
// warp per row (row = p*BB + b). 32 lanes x 6 float4 iterations = 768 floats.
__global__ void __launch_bounds__(256) kb_anom(const float* __restrict__ x,
                                               const float* __restrict__ text) {
    const int warp = threadIdx.x >> 5;
    const int lane = threadIdx.x & 31;
    const int r = blockIdx.x * 8 + warp;      // grid = ROWS/8 = 4608
    const int b = r & (BB - 1);

    const float4* xr = (const float4*)x + (size_t)(r + BB) * (DD / 4);
    const float4* tr = (const float4*)text + (size_t)b * (DD / 4);

    float ss = 0.f, st = 0.f, tt = 0.f;
    #pragma unroll
    for (int it = 0; it < 6; it++) {
        const float4 xv = __ldg(xr + it * 32 + lane);
        const float4 tv = __ldg(tr + it * 32 + lane);
        ss += xv.x * xv.x + xv.y * xv.y + xv.z * xv.z + xv.w * xv.w;
        st += xv.x * tv.x + xv.y * tv.y + xv.z * tv.z + xv.w * tv.w;
        tt += tv.x * tv.x + tv.y * tv.y + tv.z * tv.z + tv.w * tv.w;
    }
    ss = warp_sum(ss);
    st = warp_sum(st);
    tt = warp_sum(tt);

    if (lane == 0) {
        const float pn = sqrtf(ss);
        const float tn = sqrtf(tt);
        const float sim = st / (fmaxf(pn, EPSC) * fmaxf(tn, EPSC));
        g_anom[r] = pn * (1.0f - fmaxf(sim, 0.0f));
    }
}

// ---------------- Kernel C: global stats + gate -------------------------------
// single block, 1024 threads. 3 light passes over 36864 elements (L2 resident).
__global__ void __launch_bounds__(1024) kc_stats() {
    const int tid = threadIdx.x;
    const int lane = tid & 31, w = tid >> 5;
    __shared__ float p0[32], p1[32], p2[32];
    __shared__ float bc[4];

    const float4* a4 = (const float4*)g_anom;
    const float4* f4 = (const float4*)g_fg;

    // pass 1: n (bg count), s1 = sum(bg*a), max(a)
    float n = 0.f, s1 = 0.f, mx = -3.0e38f;
    for (int i = tid; i < ROWS / 4; i += 1024) {
        const float4 av = a4[i];
        const float4 fv = f4[i];
        float bg;
        bg = 1.f - fv.x; n += bg; s1 += bg * av.x; mx = fmaxf(mx, av.x);
        bg = 1.f - fv.y; n += bg; s1 += bg * av.y; mx = fmaxf(mx, av.y);
        bg = 1.f - fv.z; n += bg; s1 += bg * av.z; mx = fmaxf(mx, av.z);
        bg = 1.f - fv.w; n += bg; s1 += bg * av.w; mx = fmaxf(mx, av.w);
    }
    n = warp_sum(n); s1 = warp_sum(s1); mx = warp_max(mx);
    if (lane == 0) { p0[w] = n; p1[w] = s1; p2[w] = mx; }
    __syncthreads();
    if (w == 0) {
        float a = warp_sum(p0[lane]);
        float b = warp_sum(p1[lane]);
        float c = warp_max(p2[lane]);
        if (lane == 0) { bc[0] = a; bc[1] = b; bc[2] = c; }
    }
    __syncthreads();
    const float N  = bc[0];
    const float mu = bc[1] / fmaxf(N, 1.0f);
    const float MX = bc[2];

    // pass 2: s2 = sum(bg*(a-mu)^2)
    float s2 = 0.f;
    for (int i = tid; i < ROWS / 4; i += 1024) {
        const float4 av = a4[i];
        const float4 fv = f4[i];
        float d;
        d = av.x - mu; s2 += (1.f - fv.x) * d * d;
        d = av.y - mu; s2 += (1.f - fv.y) * d * d;
        d = av.z - mu; s2 += (1.f - fv.z) * d * d;
        d = av.w - mu; s2 += (1.f - fv.w) * d * d;
    }
    s2 = warp_sum(s2);
    if (lane == 0) p0[w] = s2;
    __syncthreads();
    if (w == 0) {
        float a = warp_sum(p0[lane]);
        if (lane == 0) {
            const float var = a / fmaxf(N - 1.0f, 1.0f);
            bc[3] = (N > 0.f) ? (mu + BETA_C * sqrtf(var)) : MX;
        }
    }
    __syncthreads();
    const float thr = bc[3];

    // pass 3: gate = fg + (1-fg)*sigmoid(GAMMA*(thr - a))
    float4* g4 = (float4*)g_gate;
    for (int i = tid; i < ROWS / 4; i += 1024) {
        const float4 av = a4[i];
        const float4 fv = f4[i];
        float4 gv;
        gv.x = fv.x + (1.f - fv.x) * (1.0f / (1.0f + __expf(-GAMMA_C * (thr - av.x))));
        gv.y = fv.y + (1.f - fv.y) * (1.0f / (1.0f + __expf(-GAMMA_C * (thr - av.y))));
        gv.z = fv.z + (1.f - fv.z) * (1.0f / (1.0f + __expf(-GAMMA_C * (thr - av.z))));
        gv.w = fv.w + (1.f - fv.w) * (1.0f / (1.0f + __expf(-GAMMA_C * (thr - av.w))));
        g4[i] = gv;
    }
}

// ---------------- Kernel D: coeff + proj + blend (fused) ----------------------
// block = 192 threads: one float4 per thread spans D=768. pc (8x768) lives in
// registers (4 floats per k per thread), amortized over 32 rows per block.
// Per row: packed-f32x2 coeff partials -> butterfly warp sums -> 2-stage smem
// reduction -> broadcast -> packed proj + blend -> float4 store.
// Rows processed in REVERSE global order so the x tail (freshest in L2 after
// kernel B's streaming read) is re-read while still resident.
__global__ void __launch_bounds__(192) kd_out(const float* __restrict__ x,
                                              const float* __restrict__ pc,
                                              float* __restrict__ out) {
    const int tid = threadIdx.x;
    const int warp = tid >> 5;
    const int lane = tid & 31;

    u64 pc0[KK], pc1[KK];
    #pragma unroll
    for (int k = 0; k < KK; k++) {
        const float4 v = __ldg((const float4*)pc + k * 192 + tid);
        pc0[k] = pk2(v.x, v.y);
        pc1[k] = pk2(v.z, v.w);
    }

    __shared__ float redp[48];               // [warp][k]
    __shared__ __align__(16) float cfin[8];  // final coeffs (broadcast)

    const int base = (DBLK - 1 - (int)blockIdx.x) * 32;
    for (int i = 31; i >= 0; i--) {
        const int r = base + i;
        const float4 xv = __ldg((const float4*)x + (size_t)(r + BB) * (DD / 4) + tid);
        const u64 x0 = pk2(xv.x, xv.y);
        const u64 x1 = pk2(xv.z, xv.w);

        // coefficient partials: c_k = sum_d x[d]*pc[k][d]
        float cp[KK];
        #pragma unroll
        for (int k = 0; k < KK; k++) {
            const u64 acc = f2fma(x1, pc1[k], f2mul(x0, pc0[k]));
            float lo, hi; up2(acc, lo, hi);
            cp[k] = warp_sum(lo + hi);
        }
        if (lane == 0) {
            #pragma unroll
            for (int k = 0; k < KK; k++) redp[warp * 8 + k] = cp[k];
        }
        __syncthreads();
        if (tid < 8) {
            cfin[tid] = redp[tid] + redp[8 + tid] + redp[16 + tid] +
                        redp[24 + tid] + redp[32 + tid] + redp[40 + tid];
        }
        __syncthreads();

        const float g  = __ldg(&g_gate[r]);
        const float4 cA = *(const float4*)cfin;
        const float4 cB = *(const float4*)(cfin + 4);

        u64 cc = pk2(cA.x, cA.x);
        u64 q0 = f2mul(cc, pc0[0]);
        u64 q1 = f2mul(cc, pc1[0]);
        cc = pk2(cA.y, cA.y); q0 = f2fma(cc, pc0[1], q0); q1 = f2fma(cc, pc1[1], q1);
        cc = pk2(cA.z, cA.z); q0 = f2fma(cc, pc0[2], q0); q1 = f2fma(cc, pc1[2], q1);
        cc = pk2(cA.w, cA.w); q0 = f2fma(cc, pc0[3], q0); q1 = f2fma(cc, pc1[3], q1);
        cc = pk2(cB.x, cB.x); q0 = f2fma(cc, pc0[4], q0); q1 = f2fma(cc, pc1[4], q1);
        cc = pk2(cB.y, cB.y); q0 = f2fma(cc, pc0[5], q0); q1 = f2fma(cc, pc1[5], q1);
        cc = pk2(cB.z, cB.z); q0 = f2fma(cc, pc0[6], q0); q1 = f2fma(cc, pc1[6], q1);
        cc = pk2(cB.w, cB.w); q0 = f2fma(cc, pc0[7], q0); q1 = f2fma(cc, pc1[7], q1);

        const float og = 1.0f - g;
        const u64 g2  = pk2(g, g);
        const u64 og2 = pk2(og, og);
        const u64 o0 = f2fma(g2, x0, f2mul(og2, q0));
        const u64 o1 = f2fma(g2, x1, f2mul(og2, q1));
        float a0, a1, a2, a3;
        up2(o0, a0, a1);
        up2(o1, a2, a3);
        ((float4*)out)[(size_t)(r + BB) * (DD / 4) + tid] = make_float4(a0, a1, a2, a3);
    }
}

// ---------------- launch ------------------------------------------------------
extern "C" void kernel_launch(void* const* d_in, const int* in_sizes, int n_in,
                              void* d_out, int out_size) {
    const float* x    = (const float*)d_in[0];
    const float* attn = (const float*)d_in[1];
    const float* text = (const float*)d_in[2];
    const float* pc   = (const float*)d_in[3];
    float* out = (float*)d_out;

    // cls token pass-through: out[0] = x[0]  (64*768 floats)
    cudaMemcpyAsync(out, x, (size_t)BB * DD * sizeof(float),
                    cudaMemcpyDeviceToDevice);

    ka_fg<<<BB, 576>>>(attn);
    kb_anom<<<ROWS / 8, 256>>>(x, text);
    kc_stats<<<1, 1024>>>();
    kd_out<<<DBLK, 192>>>(x, pc, out);
}

// round 8
// speedup vs baseline: 1.3965x; 1.3965x over previous
#include <cuda_runtime.h>
#include <cstdint>
#include <cstddef>

// Problem constants
#define SEQ   577
#define BB    64
#define DD    768
#define HH    12
#define KK    8
#define PP    576            // SEQ-1
#define ROWS  (PP*BB)        // 36864
#define S2    (SEQ*SEQ)      // 332929
#define EPSC  1e-8f
#define BETA_C  3.0f
#define GAMMA_C 5.0f

#define DBLK  1152           // kernel D blocks: 1152*32 = 36864 rows

// ---------------- scratch (static device globals; no allocation) -------------
__device__ __align__(16) float g_fg[ROWS];
__device__ __align__(16) float g_anom[ROWS];
__device__ __align__(16) float g_gate[ROWS];

// ---------------- helpers ----------------------------------------------------
typedef unsigned long long u64;

__device__ __forceinline__ float warp_sum(float v) {
    v += __shfl_xor_sync(0xffffffffu, v, 16);
    v += __shfl_xor_sync(0xffffffffu, v, 8);
    v += __shfl_xor_sync(0xffffffffu, v, 4);
    v += __shfl_xor_sync(0xffffffffu, v, 2);
    v += __shfl_xor_sync(0xffffffffu, v, 1);
    return v;
}
__device__ __forceinline__ float warp_max(float v) {
    v = fmaxf(v, __shfl_xor_sync(0xffffffffu, v, 16));
    v = fmaxf(v, __shfl_xor_sync(0xffffffffu, v, 8));
    v = fmaxf(v, __shfl_xor_sync(0xffffffffu, v, 4));
    v = fmaxf(v, __shfl_xor_sync(0xffffffffu, v, 2));
    v = fmaxf(v, __shfl_xor_sync(0xffffffffu, v, 1));
    return v;
}
__device__ __forceinline__ u64 pk2(float lo, float hi) {
    u64 r; asm("mov.b64 %0, {%1,%2};" : "=l"(r) : "f"(lo), "f"(hi)); return r;
}
__device__ __forceinline__ void up2(u64 v, float& lo, float& hi) {
    asm("mov.b64 {%0,%1}, %2;" : "=f"(lo), "=f"(hi) : "l"(v));
}
__device__ __forceinline__ u64 f2mul(u64 a, u64 b) {
    u64 d; asm("mul.rn.f32x2 %0, %1, %2;" : "=l"(d) : "l"(a), "l"(b)); return d;
}
__device__ __forceinline__ u64 f2fma(u64 a, u64 b, u64 c) {
    u64 d; asm("fma.rn.f32x2 %0, %1, %2, %3;" : "=l"(d) : "l"(a), "l"(b), "l"(c)); return d;
}

// 8-value warp reduction: input cp[0..7] per lane; output = full 32-lane sum of
// cp[k] held by every lane with (lane>>2)&7 == k. 9 shuffles total.
__device__ __forceinline__ float warp_sum8(const float* cp, int lane) {
    const bool b4 = (lane & 16) != 0;
    const bool b3 = (lane & 8) != 0;
    const bool b2 = (lane & 4) != 0;
    float v0, v1, v2, v3;
    {
        float s, r;
        s = b4 ? cp[0] : cp[4]; r = __shfl_xor_sync(0xffffffffu, s, 16);
        v0 = (b4 ? cp[4] : cp[0]) + r;
        s = b4 ? cp[1] : cp[5]; r = __shfl_xor_sync(0xffffffffu, s, 16);
        v1 = (b4 ? cp[5] : cp[1]) + r;
        s = b4 ? cp[2] : cp[6]; r = __shfl_xor_sync(0xffffffffu, s, 16);
        v2 = (b4 ? cp[6] : cp[2]) + r;
        s = b4 ? cp[3] : cp[7]; r = __shfl_xor_sync(0xffffffffu, s, 16);
        v3 = (b4 ? cp[7] : cp[3]) + r;
    }
    float w0, w1;
    {
        float s, r;
        s = b3 ? v0 : v2; r = __shfl_xor_sync(0xffffffffu, s, 8);
        w0 = (b3 ? v2 : v0) + r;
        s = b3 ? v1 : v3; r = __shfl_xor_sync(0xffffffffu, s, 8);
        w1 = (b3 ? v3 : v1) + r;
    }
    float u;
    {
        float s = b2 ? w0 : w1;
        float r = __shfl_xor_sync(0xffffffffu, s, 4);
        u = (b2 ? w1 : w0) + r;
    }
    u += __shfl_xor_sync(0xffffffffu, u, 2);
    u += __shfl_xor_sync(0xffffffffu, u, 1);
    return u;   // lane holds sum for k = (lane>>2)&7
}

// ---------------- Kernel AB: fg mask + anomaly fused (independent parts) ------
// Blocks [0,64): A part (fg mask), b = blockIdx.x. Blocks [64, 64+2048): B part,
// 18 warps per block, warp per row.
__global__ void __launch_bounds__(576) kab(const float* __restrict__ x,
                                           const float* __restrict__ text,
                                           const float* __restrict__ attn) {
    const int tid = threadIdx.x;
    const int lane = tid & 31, w = tid >> 5;

    if (blockIdx.x < 64) {
        // ---- A: foreground mask ----
        __shared__ float sp[18];
        __shared__ float bcast;
        const int b = blockIdx.x;
        const int p = tid;

        const float* base = attn + (size_t)b * HH * (size_t)S2 + 1 + p;
        float a = 0.f;
        #pragma unroll
        for (int h = 0; h < HH; h++) a += __ldg(base + (size_t)h * S2);
        a *= (1.0f / 12.0f);

        float v = warp_sum(a);
        if (lane == 0) sp[w] = v;
        __syncthreads();
        if (w == 0) {
            float t = (lane < 18) ? sp[lane] : 0.f;
            t = warp_sum(t);
            if (lane == 0) bcast = t;
        }
        __syncthreads();
        const float mu = bcast * (1.0f / 576.0f);
        const float d = a - mu;
        __syncthreads();

        v = warp_sum(d * d);
        if (lane == 0) sp[w] = v;
        __syncthreads();
        if (w == 0) {
            float t = (lane < 18) ? sp[lane] : 0.f;
            t = warp_sum(t);
            if (lane == 0) bcast = t;
        }
        __syncthreads();
        const float sigma = sqrtf(bcast * (1.0f / 575.0f));

        g_fg[p * BB + b] = (a > mu + 1.5f * sigma) ? 1.0f : 0.0f;
    } else {
        // ---- B: per-row anomaly (warp per row) ----
        const int r = (blockIdx.x - 64) * 18 + w;
        const int b = r & (BB - 1);

        const float4* xr = (const float4*)x + (size_t)(r + BB) * (DD / 4);
        const float4* tr = (const float4*)text + (size_t)b * (DD / 4);

        float ss = 0.f, st = 0.f, tt = 0.f;
        #pragma unroll
        for (int it = 0; it < 6; it++) {
            const float4 xv = __ldg(xr + it * 32 + lane);
            const float4 tv = __ldg(tr + it * 32 + lane);
            ss += xv.x * xv.x + xv.y * xv.y + xv.z * xv.z + xv.w * xv.w;
            st += xv.x * tv.x + xv.y * tv.y + xv.z * tv.z + xv.w * tv.w;
            tt += tv.x * tv.x + tv.y * tv.y + tv.z * tv.z + tv.w * tv.w;
        }
        ss = warp_sum(ss);
        st = warp_sum(st);
        tt = warp_sum(tt);

        if (lane == 0) {
            const float pn = sqrtf(ss);
            const float tn = sqrtf(tt);
            const float sim = st / (fmaxf(pn, EPSC) * fmaxf(tn, EPSC));
            g_anom[r] = pn * (1.0f - fmaxf(sim, 0.0f));
        }
    }
}

// ---------------- Kernel C: global stats + gate -------------------------------
__global__ void __launch_bounds__(1024) kc_stats() {
    const int tid = threadIdx.x;
    const int lane = tid & 31, w = tid >> 5;
    __shared__ float p0[32], p1[32], p2[32];
    __shared__ float bc[4];

    const float4* a4 = (const float4*)g_anom;
    const float4* f4 = (const float4*)g_fg;

    float n = 0.f, s1 = 0.f, mx = -3.0e38f;
    for (int i = tid; i < ROWS / 4; i += 1024) {
        const float4 av = a4[i];
        const float4 fv = f4[i];
        float bg;
        bg = 1.f - fv.x; n += bg; s1 += bg * av.x; mx = fmaxf(mx, av.x);
        bg = 1.f - fv.y; n += bg; s1 += bg * av.y; mx = fmaxf(mx, av.y);
        bg = 1.f - fv.z; n += bg; s1 += bg * av.z; mx = fmaxf(mx, av.z);
        bg = 1.f - fv.w; n += bg; s1 += bg * av.w; mx = fmaxf(mx, av.w);
    }
    n = warp_sum(n); s1 = warp_sum(s1); mx = warp_max(mx);
    if (lane == 0) { p0[w] = n; p1[w] = s1; p2[w] = mx; }
    __syncthreads();
    if (w == 0) {
        float a = warp_sum(p0[lane]);
        float b = warp_sum(p1[lane]);
        float c = warp_max(p2[lane]);
        if (lane == 0) { bc[0] = a; bc[1] = b; bc[2] = c; }
    }
    __syncthreads();
    const float N  = bc[0];
    const float mu = bc[1] / fmaxf(N, 1.0f);
    const float MX = bc[2];

    float s2 = 0.f;
    for (int i = tid; i < ROWS / 4; i += 1024) {
        const float4 av = a4[i];
        const float4 fv = f4[i];
        float d;
        d = av.x - mu; s2 += (1.f - fv.x) * d * d;
        d = av.y - mu; s2 += (1.f - fv.y) * d * d;
        d = av.z - mu; s2 += (1.f - fv.z) * d * d;
        d = av.w - mu; s2 += (1.f - fv.w) * d * d;
    }
    s2 = warp_sum(s2);
    if (lane == 0) p0[w] = s2;
    __syncthreads();
    if (w == 0) {
        float a = warp_sum(p0[lane]);
        if (lane == 0) {
            const float var = a / fmaxf(N - 1.0f, 1.0f);
            bc[3] = (N > 0.f) ? (mu + BETA_C * sqrtf(var)) : MX;
        }
    }
    __syncthreads();
    const float thr = bc[3];

    float4* g4 = (float4*)g_gate;
    for (int i = tid; i < ROWS / 4; i += 1024) {
        const float4 av = a4[i];
        const float4 fv = f4[i];
        float4 gv;
        gv.x = fv.x + (1.f - fv.x) * (1.0f / (1.0f + __expf(-GAMMA_C * (thr - av.x))));
        gv.y = fv.y + (1.f - fv.y) * (1.0f / (1.0f + __expf(-GAMMA_C * (thr - av.y))));
        gv.z = fv.z + (1.f - fv.z) * (1.0f / (1.0f + __expf(-GAMMA_C * (thr - av.z))));
        gv.w = fv.w + (1.f - fv.w) * (1.0f / (1.0f + __expf(-GAMMA_C * (thr - av.w))));
        g4[i] = gv;
    }
}

// ---------------- Kernel D: coeff + proj + blend (fused) ----------------------
// 192 threads: thread owns 4 columns of D=768; pc in 32 regs. 4-row batching:
// 4 independent x loads, per-row 9-shuffle multi-value reduction (warp_sum8),
// ONE syncthreads pair per 4 rows. Reverse block order for L2 reuse of x.
__global__ void __launch_bounds__(192) kd_out(const float* __restrict__ x,
                                              const float* __restrict__ pc,
                                              float* __restrict__ out) {
    const int tid = threadIdx.x;
    const int warp = tid >> 5;
    const int lane = tid & 31;

    u64 pc0[KK], pc1[KK];
    #pragma unroll
    for (int k = 0; k < KK; k++) {
        const float4 v = __ldg((const float4*)pc + k * 192 + tid);
        pc0[k] = pk2(v.x, v.y);
        pc1[k] = pk2(v.z, v.w);
    }

    __shared__ float redp[4 * 6 * 8];            // [row][warp][k]
    __shared__ __align__(16) float cfin[4 * 8];  // [row][k]

    const int base = (DBLK - 1 - (int)blockIdx.x) * 32;

    for (int i0 = 0; i0 < 32; i0 += 4) {
        // batched x loads (MLP=4)
        u64 x0[4], x1[4];
        #pragma unroll
        for (int j = 0; j < 4; j++) {
            const float4 xv = __ldg((const float4*)x +
                                    (size_t)(base + i0 + j + BB) * (DD / 4) + tid);
            x0[j] = pk2(xv.x, xv.y);
            x1[j] = pk2(xv.z, xv.w);
        }

        // per-row coefficient partials + 9-shuffle reduction
        float ured[4];
        #pragma unroll
        for (int j = 0; j < 4; j++) {
            float cp[KK];
            #pragma unroll
            for (int k = 0; k < KK; k++) {
                const u64 acc = f2fma(x1[j], pc1[k], f2mul(x0[j], pc0[k]));
                float lo, hi; up2(acc, lo, hi);
                cp[k] = lo + hi;
            }
            ured[j] = warp_sum8(cp, lane);   // lane holds k=(lane>>2)&7
        }

        if ((lane & 3) == 0) {
            const int k = lane >> 2;
            #pragma unroll
            for (int j = 0; j < 4; j++)
                redp[(j * 6 + warp) * 8 + k] = ured[j];
        }
        __syncthreads();
        if (tid < 32) {
            const int row = tid >> 3, k = tid & 7;
            float s = 0.f;
            #pragma unroll
            for (int ww = 0; ww < 6; ww++) s += redp[(row * 6 + ww) * 8 + k];
            cfin[row * 8 + k] = s;
        }
        __syncthreads();

        // projection + blend + store for 4 rows
        #pragma unroll
        for (int j = 0; j < 4; j++) {
            const int r = base + i0 + j;
            const float g = __ldg(&g_gate[r]);
            const float4 cA = *(const float4*)(cfin + j * 8);
            const float4 cB = *(const float4*)(cfin + j * 8 + 4);

            u64 cc = pk2(cA.x, cA.x);
            u64 q0 = f2mul(cc, pc0[0]);
            u64 q1 = f2mul(cc, pc1[0]);
            cc = pk2(cA.y, cA.y); q0 = f2fma(cc, pc0[1], q0); q1 = f2fma(cc, pc1[1], q1);
            cc = pk2(cA.z, cA.z); q0 = f2fma(cc, pc0[2], q0); q1 = f2fma(cc, pc1[2], q1);
            cc = pk2(cA.w, cA.w); q0 = f2fma(cc, pc0[3], q0); q1 = f2fma(cc, pc1[3], q1);
            cc = pk2(cB.x, cB.x); q0 = f2fma(cc, pc0[4], q0); q1 = f2fma(cc, pc1[4], q1);
            cc = pk2(cB.y, cB.y); q0 = f2fma(cc, pc0[5], q0); q1 = f2fma(cc, pc1[5], q1);
            cc = pk2(cB.z, cB.z); q0 = f2fma(cc, pc0[6], q0); q1 = f2fma(cc, pc1[6], q1);
            cc = pk2(cB.w, cB.w); q0 = f2fma(cc, pc0[7], q0); q1 = f2fma(cc, pc1[7], q1);

            const float og = 1.0f - g;
            const u64 g2  = pk2(g, g);
            const u64 og2 = pk2(og, og);
            const u64 o0 = f2fma(g2, x0[j], f2mul(og2, q0));
            const u64 o1 = f2fma(g2, x1[j], f2mul(og2, q1));
            float a0, a1, a2, a3;
            up2(o0, a0, a1);
            up2(o1, a2, a3);
            ((float4*)out)[(size_t)(r + BB) * (DD / 4) + tid] =
                make_float4(a0, a1, a2, a3);
        }
        // no extra barrier needed: next iter's redp writes are fenced by the
        // barriers above before cfin is rewritten.
    }
}

// ---------------- launch ------------------------------------------------------
extern "C" void kernel_launch(void* const* d_in, const int* in_sizes, int n_in,
                              void* d_out, int out_size) {
    const float* x    = (const float*)d_in[0];
    const float* attn = (const float*)d_in[1];
    const float* text = (const float*)d_in[2];
    const float* pc   = (const float*)d_in[3];
    float* out = (float*)d_out;

    // cls token pass-through: out[0] = x[0]
    cudaMemcpyAsync(out, x, (size_t)BB * DD * sizeof(float),
                    cudaMemcpyDeviceToDevice);

    kab<<<64 + 2048, 576>>>(x, text, attn);
    kc_stats<<<1, 1024>>>();
    kd_out<<<DBLK, 192>>>(x, pc, out);
}